// round 5
// baseline (speedup 1.0000x reference)
#include <cuda_runtime.h>
#include <math.h>

// NeRF-style renderer: B=1, H=W=200, FOCAL=300, NEAR=2, FAR=6, S=128, F=8.
// 8 threads per pixel, each composites a 16-sample segment; exact segmented
// combine via warp shuffles (width-8 groups).
// exp/sigmoid use raw ex2/rcp with log2(e) folded into staged constants.
// Output: color_map [200*200*3] then depth_map [200*200] (fp32).

#define H 200
#define W 200
#define NPIX (H * W)
#define S 128
#define F 8
#define SEG 8                 // threads per pixel
#define SPT (S / SEG)         // samples per thread = 16
#define FOCAL 300.0f
#define NEARP 2.0f
#define FARP 6.0f
#define L2E 1.4426950408889634f

__device__ __forceinline__ float ex2f(float x) {
    float r;
    asm("ex2.approx.f32 %0, %1;" : "=f"(r) : "f"(x));
    return r;
}
__device__ __forceinline__ float rcpf(float x) {
    float r;
    asm("rcp.approx.f32 %0, %1;" : "=f"(r) : "f"(x));
    return r;
}

__global__ __launch_bounds__(128, 8)
void render_kernel(const float* __restrict__ positions,
                   const float* __restrict__ forwards,
                   const float* __restrict__ ups,
                   const float* __restrict__ normal,
                   const float* __restrict__ Wf,
                   const float* __restrict__ bf,
                   const float* __restrict__ Wd,
                   const float* __restrict__ bd,
                   const float* __restrict__ Wc,
                   const float* __restrict__ bc,
                   float* __restrict__ out)
{
    // ---- shared staging ----
    // (t, dl2) fused; sample s = q*SPT + i lives at slot i*SEG + q.
    // dl2 = -(delta_raw) * log2(e)  so  exp(-d*delta*dn) = ex2(d * dl2 * dn).
    __shared__ float2 s_td[S];
    __shared__ float s_Wf[3][F];
    __shared__ float s_WdF[F];
    __shared__ float s_negWcF[F][3];   // -Wc_feat * log2(e)
    __shared__ float s_cam[12];        // right(3), up(3), fwd(3), pos(3)
    __shared__ float s_Wd3[3];
    __shared__ float s_negWc3[3][3];   // -Wc_dir * log2(e)
    __shared__ float s_negbc[3];       // -bc * log2(e)
    __shared__ float s_bf[F];
    __shared__ float s_bd;

    const int tid = threadIdx.x;

    if (tid < S) {
        float n0 = normal[tid];
        int xi = (tid % SPT) * SEG + (tid / SPT);   // transposed slot
        float t = NEARP + n0 * (FARP - NEARP);
        float dl = (tid < S - 1) ? (normal[tid + 1] - n0) * (FARP - NEARP)
                                 : 1e10f;
        s_td[xi] = make_float2(t, -dl * L2E);
    }
    if (tid < 24) s_Wf[tid / F][tid % F] = Wf[tid];
    if (tid >= 32 && tid < 32 + F) {
        int j = tid - 32;
        s_WdF[j] = Wd[3 + j];
        s_bf[j] = bf[j];
    }
    if (tid >= 40 && tid < 40 + 24) {
        int k = tid - 40;
        s_negWcF[k / 3][k % 3] = -L2E * Wc[(3 + k / 3) * 3 + (k % 3)];
    }
    if (tid == 0) {
        float ux = ups[0], uy = ups[1], uz = ups[2];
        float fx = forwards[0], fy = forwards[1], fz = forwards[2];
        s_cam[0] = uy * fz - uz * fy;
        s_cam[1] = uz * fx - ux * fz;
        s_cam[2] = ux * fy - uy * fx;
        s_cam[3] = ux; s_cam[4] = uy; s_cam[5] = uz;
        s_cam[6] = fx; s_cam[7] = fy; s_cam[8] = fz;
        s_cam[9] = positions[0]; s_cam[10] = positions[1]; s_cam[11] = positions[2];
        s_Wd3[0] = Wd[0]; s_Wd3[1] = Wd[1]; s_Wd3[2] = Wd[2];
        s_bd = bd[0];
        #pragma unroll
        for (int j = 0; j < 3; j++) {
            s_negbc[j] = -L2E * bc[j];
            #pragma unroll
            for (int i = 0; i < 3; i++) s_negWc3[j][i] = -L2E * Wc[j * 3 + i];
        }
    }
    __syncthreads();

    const int gtid = blockIdx.x * blockDim.x + tid;   // 320,000 threads exactly
    const int pix = gtid >> 3;
    const int q = gtid & 7;                            // segment id

    const int h = pix / W;
    const int w = pix - h * W;

    const float a = ((float)h - (H * 0.5f - 0.5f)) * (1.0f / FOCAL);
    const float b = -((float)w - (W * 0.5f - 0.5f)) * (1.0f / FOCAL);

    const float dx = a * s_cam[0] + b * s_cam[3] + s_cam[6];
    const float dy = a * s_cam[1] + b * s_cam[4] + s_cam[7];
    const float dz = a * s_cam[2] + b * s_cam[5] + s_cam[8];
    const float dn = sqrtf(dx * dx + dy * dy + dz * dz);

    const float px = s_cam[9], py = s_cam[10], pz = s_cam[11];

    // ---- hoist loop invariants into registers ----
    float dirF[F], baseF[F], wdF[F], wc0[F], wc1[F], wc2[F];
    #pragma unroll
    for (int j = 0; j < F; j++) {
        const float w0 = s_Wf[0][j], w1 = s_Wf[1][j], w2 = s_Wf[2][j];
        dirF[j]  = dx * w0 + dy * w1 + dz * w2;
        baseF[j] = px * w0 + py * w1 + pz * w2 + s_bf[j];
        wdF[j]   = s_WdF[j];
        wc0[j]   = s_negWcF[j][0];
        wc1[j]   = s_negWcF[j][1];
        wc2[j]   = s_negWcF[j][2];
    }
    const float dird  = dx * s_Wd3[0] + dy * s_Wd3[1] + dz * s_Wd3[2];
    const float based = px * s_Wd3[0] + py * s_Wd3[1] + pz * s_Wd3[2] + s_bd;

    const float nb0 = dx * s_negWc3[0][0] + dy * s_negWc3[1][0] + dz * s_negWc3[2][0] + s_negbc[0];
    const float nb1 = dx * s_negWc3[0][1] + dy * s_negWc3[1][1] + dz * s_negWc3[2][1] + s_negbc[1];
    const float nb2 = dx * s_negWc3[0][2] + dy * s_negWc3[1][2] + dz * s_negWc3[2][2] + s_negbc[2];

    // ---- local segment compositing (T starts at 1) ----
    float T = 1.0f;
    float c0 = 0.0f, c1 = 0.0f, c2 = 0.0f, depth = 0.0f;

    const float2* td = s_td + q;

    #pragma unroll
    for (int i = 0; i < SPT; i++) {
        const float2 tdl = td[i * SEG];
        const float t = tdl.x;

        float f[F];
        #pragma unroll
        for (int j = 0; j < F; j++)
            f[j] = fmaxf(fmaf(t, dirF[j], baseF[j]), 0.0f);

        float d = fmaf(t, dird, based);
        #pragma unroll
        for (int j = 0; j < F; j++)
            d = fmaf(f[j], wdF[j], d);
        d = fmaxf(d, 0.0f);

        // e = exp(-d*delta*dn) = ex2(d * dl2 * dn)
        const float e  = ex2f(d * (tdl.y * dn));
        const float Tn = T * e;
        const float wgt = T - Tn;
        T = Tn;

        float x0 = nb0, x1 = nb1, x2 = nb2;
        #pragma unroll
        for (int j = 0; j < F; j++) {
            x0 = fmaf(f[j], wc0[j], x0);
            x1 = fmaf(f[j], wc1[j], x1);
            x2 = fmaf(f[j], wc2[j], x2);
        }
        // sigmoid(z) with z-arg pre-scaled by -log2(e): g = 1/(1+2^x)
        const float g0 = rcpf(1.0f + ex2f(x0));
        const float g1 = rcpf(1.0f + ex2f(x1));
        const float g2 = rcpf(1.0f + ex2f(x2));

        c0 = fmaf(wgt, g0, c0);
        c1 = fmaf(wgt, g1, c1);
        c2 = fmaf(wgt, g2, c2);
        depth += wgt;
    }

    // ---- segmented combine across the 8 threads of this pixel ----
    const unsigned mask = 0xFFFFFFFFu;
    float p = 1.0f;
    #pragma unroll
    for (int r = 0; r < SEG - 1; r++) {
        const float Tr = __shfl_sync(mask, T, r, SEG);
        if (q > r) p *= Tr;
    }
    c0 *= p; c1 *= p; c2 *= p; depth *= p;

    #pragma unroll
    for (int off = 1; off < SEG; off <<= 1) {
        c0    += __shfl_xor_sync(mask, c0, off, SEG);
        c1    += __shfl_xor_sync(mask, c1, off, SEG);
        c2    += __shfl_xor_sync(mask, c2, off, SEG);
        depth += __shfl_xor_sync(mask, depth, off, SEG);
    }

    if (q == 0) {
        out[pix * 3 + 0] = c0;
        out[pix * 3 + 1] = c1;
        out[pix * 3 + 2] = c2;
        out[NPIX * 3 + pix] = depth;
    }
}

extern "C" void kernel_launch(void* const* d_in, const int* in_sizes, int n_in,
                              void* d_out, int out_size)
{
    const float* positions = (const float*)d_in[0];
    const float* forwards  = (const float*)d_in[1];
    const float* ups       = (const float*)d_in[2];
    const float* normal    = (const float*)d_in[3];
    const float* Wf        = (const float*)d_in[4];
    const float* bf        = (const float*)d_in[5];
    const float* Wd        = (const float*)d_in[6];
    const float* bd        = (const float*)d_in[7];
    const float* Wc        = (const float*)d_in[8];
    const float* bc        = (const float*)d_in[9];
    float* out = (float*)d_out;

    const int threads = 128;
    const int blocks = (NPIX * SEG) / threads;   // 2500
    render_kernel<<<blocks, threads>>>(positions, forwards, ups, normal,
                                       Wf, bf, Wd, bd, Wc, bc, out);
}